// round 13
// baseline (speedup 1.0000x reference)
#include <cuda_runtime.h>
#include <math.h>

#define Sn 128
#define Pn 32
#define HDn 32
#define EDn 16
#define GHn 72
#define GOn 8
#define MDn 64
#define Tn 8
#define Bn (Sn*Pn)
#define NT 1024

typedef unsigned long long ull;

// ---- byte offsets into dynamic smem (16B aligned) ----
#define OFF_WL      0        // ulonglong2 [32][48]   24576
#define OFF_BIF     24576    // ull [32]              256
#define OFF_BGO     24832    // ull [32]              256
#define OFF_WHP     25088    // float2 [32]           256
#define OFF_BHP     25344    // float [2]             16
#define OFF_WSE     25360    // float [32]            128
#define OFF_BSE     25488    // float [16]            64
#define OFF_W1BT    25552    // float2 [2*36][32]     18432
#define OFF_WCC     43984    // float2 [2][72]        1152
#define OFF_C0      45136    // float [2][72]         576
#define OFF_WM1P    45712    // ulonglong2 [32][24]   12288
#define OFF_BM1     58000    // ull [32]              256
#define OFF_WM2P    58256    // ulonglong2 [16][32]   8192
#define OFF_BM2     66448    // ull [16]              128
#define OFF_W2      66576    // float [2][72][8]      4608   (per-d channel pairs)
#define OFF_H2T     71184    // float [32][33]        4224
#define OFF_HIDT    75408    // float [32][33]        4224
#define OFF_XVT     79632    // float [16][33]        2112
#define OFF_POS     81744    // float [2][32]         256
#define OFF_RELP    82000    // float [2][32]         256
#define OFF_PSUM    82256    // float [5][2]          64
#define OFF_GTMP    82320    // int [32]              128
#define OFF_MSK     82448    // unsigned [2][32]      256
#define OFF_CINV    82704    // float [2][32]         256
#define OFF_GMASK   82960    // unsigned [8]          48
#define OFF_U       83008    // float [64][76]        19456
#define OFF_MIXA    102464   // float [64][144]       36864  row: [plane0: -q | plane1: .5u-q]
#define OFF_SU      139328   // float [64][72]        18432
#define OFF_ZR      157760   // float [64][288]       73728
#define SMEM_TOTAL  231488
// overlays (lifetime-disjoint):
#define OFF_UB      OFF_ZR            // float [144][33] 19008  (ubase; dead before Z writes)
#define OFF_GSUM    (OFF_ZR+19456)    // float [2][5][72] 2880  (gsum->mix; dead before Z writes)
#define OFF_MIDT    OFF_SU            // float [64][33]  8448   (MLP1->MLP2; SU dead after Z)
#define OFF_POOLT   (OFF_SU+8448)     // float [16][33]  2112   (max->MLP1)

#define USTR 76
#define ZSTR 288

__device__ __forceinline__ ull pk2(float a, float b){
  ull r; asm("mov.b64 %0,{%1,%2};" : "=l"(r) : "f"(a), "f"(b)); return r;
}
__device__ __forceinline__ void upk2(ull v, float& a, float& b){
  asm("mov.b64 {%0,%1},%2;" : "=f"(a), "=f"(b) : "l"(v));
}
__device__ __forceinline__ ull fma2(ull a, ull b, ull c){
  ull r; asm("fma.rn.f32x2 %0,%1,%2,%3;" : "=l"(r) : "l"(a), "l"(b), "l"(c)); return r;
}
__device__ __forceinline__ ull lds64(const void* p){ return *reinterpret_cast<const ull*>(p); }

__device__ __forceinline__ float sigm(float x){ return 1.0f/(1.0f + __expf(-x)); }
__device__ __forceinline__ float tanh_f(float x){
  float t = __expf(-2.0f*fabsf(x));
  float r = (1.0f - t)/(1.0f + t);
  return copysignf(r, x);
}

__global__ __launch_bounds__(NT, 1)
void dec_kernel(const float* __restrict__ last_pos, const float* __restrict__ last_pos_rel,
                const float* __restrict__ hh, const float* __restrict__ ch,
                const int* __restrict__ end_group,
                const float* __restrict__ W_se, const float* __restrict__ b_se,
                const float* __restrict__ Wih, const float* __restrict__ Whh,
                const float* __restrict__ bih, const float* __restrict__ bhh,
                const float* __restrict__ W_hp, const float* __restrict__ b_hp,
                const float* __restrict__ W_pse, const float* __restrict__ b_pse,
                const float* __restrict__ W1a, const float* __restrict__ W2a,
                const float* __restrict__ W1b, const float* __restrict__ W2b,
                const float* __restrict__ W_m1, const float* __restrict__ b_m1,
                const float* __restrict__ W_m2, const float* __restrict__ b_m2,
                float* __restrict__ out)
{
  extern __shared__ char sb[];
  ulonglong2* WL   = (ulonglong2*)(sb+OFF_WL);
  ull*      BIF    = (ull*)     (sb+OFF_BIF);
  ull*      BGO    = (ull*)     (sb+OFF_BGO);
  float2*   WHP    = (float2*)  (sb+OFF_WHP);
  float*    BHP    = (float*)   (sb+OFF_BHP);
  float*    WSE    = (float*)   (sb+OFF_WSE);
  float*    BSE    = (float*)   (sb+OFF_BSE);
  float2*   W1BT   = (float2*)  (sb+OFF_W1BT);
  float2*   WCC    = (float2*)  (sb+OFF_WCC);
  float*    C0     = (float*)   (sb+OFF_C0);
  ulonglong2* WM1P = (ulonglong2*)(sb+OFF_WM1P);
  ull*      BM1    = (ull*)     (sb+OFF_BM1);
  ulonglong2* WM2P = (ulonglong2*)(sb+OFF_WM2P);
  ull*      BM2    = (ull*)     (sb+OFF_BM2);
  float*    W2p    = (float*)   (sb+OFF_W2);
  float*    H2T    = (float*)   (sb+OFF_H2T);
  float*    HIDT   = (float*)   (sb+OFF_HIDT);
  float*    XVT    = (float*)   (sb+OFF_XVT);
  float*    POS    = (float*)   (sb+OFF_POS);
  float*    RELP   = (float*)   (sb+OFF_RELP);
  float*    PSUM   = (float*)   (sb+OFF_PSUM);
  int*      GTMP   = (int*)     (sb+OFF_GTMP);
  unsigned* MSK    = (unsigned*)(sb+OFF_MSK);
  float*    CINV   = (float*)   (sb+OFF_CINV);
  unsigned* GMASK  = (unsigned*)(sb+OFF_GMASK);
  float*    U      = (float*)   (sb+OFF_U);
  float*    MIXA   = (float*)   (sb+OFF_MIXA);
  float*    SU     = (float*)   (sb+OFF_SU);
  float*    ZR     = (float*)   (sb+OFF_ZR);
  float*    UB     = (float*)   (sb+OFF_UB);
  float*    GSUM   = (float*)   (sb+OFF_GSUM);
  float*    MIDT   = (float*)   (sb+OFF_MIDT);
  float*    POOLT  = (float*)   (sb+OFF_POOLT);

  const int tid  = threadIdx.x;
  const int base = blockIdx.x * Pn;
  const int lane = tid & 31;
  const int wp   = tid >> 5;

  // ---------------- setup ----------------
  for (int i=tid;i<HDn*48;i+=NT){
    int h=i/48, k=i%48;
    float wi,wf,wg,wo;
    if (k<EDn){
      wi=Wih[h*EDn+k]; wf=Wih[(HDn+h)*EDn+k]; wg=Wih[(2*HDn+h)*EDn+k]; wo=Wih[(3*HDn+h)*EDn+k];
    } else {
      int kk=k-EDn;
      wi=Whh[h*HDn+kk]; wf=Whh[(HDn+h)*HDn+kk]; wg=Whh[(2*HDn+h)*HDn+kk]; wo=Whh[(3*HDn+h)*HDn+kk];
    }
    ulonglong2 w; w.x=pk2(wi,wf); w.y=pk2(wg,wo);
    WL[i]=w;
  }
  if (tid < HDn){
    int h=tid;
    BIF[h]=pk2(bih[h]+bhh[h], bih[HDn+h]+bhh[HDn+h]);
    BGO[h]=pk2(bih[2*HDn+h]+bhh[2*HDn+h], bih[3*HDn+h]+bhh[3*HDn+h]);
    WHP[h]=make_float2(W_hp[h*2], W_hp[h*2+1]);
  }
  if (tid<2*EDn) WSE[tid]=W_se[tid];
  if (tid<EDn)   BSE[tid]=b_se[tid];
  if (tid<2)     BHP[tid]=b_hp[tid];
  for (int i=tid;i<2*36*HDn;i+=NT){
    int gi=i/(36*HDn); int r=i%(36*HDn); int dp=r/HDn, h=r%HDn;
    const float* W1 = gi? W1b : W1a;
    W1BT[(gi*36+dp)*32+h]=make_float2(W1[(EDn+h)*GHn+2*dp], W1[(EDn+h)*GHn+2*dp+1]);
  }
  for (int i=tid;i<2*GHn;i+=NT){
    int gi=i/GHn; int d=i%GHn;
    const float* W1 = gi? W1b : W1a;
    float wc0=0.f, wc1=0.f, c00=0.f;
    #pragma unroll
    for (int k=0;k<EDn;k++){
      float w=W1[k*GHn+d];
      wc0 += W_pse[k]*w;
      wc1 += W_pse[EDn+k]*w;
      c00 += b_pse[k]*w;
    }
    WCC[i]=make_float2(wc0,wc1); C0[i]=c00;
  }
  // W2 plain per-d: W2p[gi][d][c]
  for (int i=tid;i<2*GHn*GOn;i+=NT){
    int gi=i/(GHn*GOn); int rc=i%(GHn*GOn);
    W2p[i] = (gi? W2b : W2a)[rc];
  }
  for (int i=tid;i<32*24;i+=NT){
    int mp=i/24, k2=i%24; int k0=2*k2;
    ulonglong2 w;
    w.x = pk2(W_m1[k0*MDn+2*mp],     W_m1[k0*MDn+2*mp+1]);
    w.y = pk2(W_m1[(k0+1)*MDn+2*mp], W_m1[(k0+1)*MDn+2*mp+1]);
    WM1P[i]=w;
  }
  if (tid<MDn/2) BM1[tid]=pk2(b_m1[2*tid], b_m1[2*tid+1]);
  for (int i=tid;i<16*32;i+=NT){
    int hp=i/32, k2=i%32; int k0=2*k2;
    ulonglong2 w;
    w.x = pk2(W_m2[k0*HDn+2*hp],     W_m2[k0*HDn+2*hp+1]);
    w.y = pk2(W_m2[(k0+1)*HDn+2*hp], W_m2[(k0+1)*HDn+2*hp+1]);
    WM2P[i]=w;
  }
  if (tid<16) BM2[tid]=pk2(b_m2[2*tid], b_m2[2*tid+1]);
  for (int i=tid;i<Pn*HDn;i+=NT){ int p=i>>5, h=i&31; HIDT[h*33+p]=hh[base*HDn+i]; }
  for (int i=tid;i<Pn*EDn;i+=NT){ int p=i>>4, e=i&15;
    float r0=last_pos_rel[(base+p)*2], r1=last_pos_rel[(base+p)*2+1];
    XVT[e*33+p] = r0*W_se[e] + r1*W_se[EDn+e] + b_se[e]; }
  if (tid<64){ int dim=tid>>5, p=tid&31; POS[dim*32+p]=last_pos[(base+p)*2+dim]; }
  if (tid<Pn) GTMP[tid]=end_group[base+tid];
  for (int i=tid;i<Pn*HDn;i+=NT) ZR[i]=ch[base*HDn+i];
  __syncthreads();

  float creg = ZR[lane*32 + wp];   // c-state in regs (p=lane, h=wp)
  if (tid < Pn){
    int gme = GTMP[tid];
    unsigned ms=0u, md=0u;
    #pragma unroll
    for (int j=0;j<Pn;j++){
      bool samev = ((gme==GTMP[j]) && (gme!=0)) || (j==tid);
      bool diffv = (!samev) || (j==tid);
      ms |= (samev?1u:0u) << j;
      md |= (diffv?1u:0u) << j;
    }
    MSK[tid]=ms; MSK[Pn+tid]=md;
    CINV[tid]=1.0f/(float)__popc(ms);
    CINV[Pn+tid]=1.0f/(float)__popc(md);
  }
  if (tid < 8){
    unsigned gm=0u;
    if (tid>=1 && tid<=4){
      for (int j=0;j<Pn;j++) if (GTMP[j]==tid) gm |= 1u<<j;
    }
    GMASK[tid]=gm;
  }
  __syncthreads();

  // ---------------- time loop ----------------
  for (int t=0; t<Tn; t++){
    // ---- LSTM: warp=h, lane=p ----
    {
      const int h=wp, p=lane;
      const ulonglong2* wrow = WL + h*48;
      ull aif = BIF[h];
      ull ago = BGO[h];
      #pragma unroll
      for (int k=0;k<EDn;k++){
        ulonglong2 wv = wrow[k];
        float av = XVT[k*33+p];
        ull vv = pk2(av,av);
        aif=fma2(vv,wv.x,aif); ago=fma2(vv,wv.y,ago);
      }
      #pragma unroll
      for (int k=0;k<HDn;k++){
        ulonglong2 wv = wrow[EDn+k];
        float av = HIDT[k*33+p];
        ull vv = pk2(av,av);
        aif=fma2(vv,wv.x,aif); ago=fma2(vv,wv.y,ago);
      }
      float ai,af,ag,ao; upk2(aif,ai,af); upk2(ago,ag,ao);
      float c2 = sigm(af)*creg + sigm(ai)*tanh_f(ag);
      float h2v = sigm(ao)*tanh_f(c2);
      creg = c2;
      H2T[h*33+p]=h2v;
    }
    __syncthreads();

    // ---- ubase fused: each warp does 2-3 (gi,dp) columns in ONE H2 pass;
    //      warps 30/31 also accumulate rel_pos in the same pass ----
    {
      const int p0 = wp;                         // it0: gi=0, dp=wp
      const int itB = wp+32; const int g1 = itB/36; const int p1 = itB-36*g1;
      const int p2 = wp+28;                      // it2: gi=1 (only wp<8)
      const bool has2 = (wp < 8);
      const bool isrp = (wp >= 30);
      const float2* w0r = W1BT + p0*32;
      const float2* w1r = W1BT + (g1*36+p1)*32;
      const float2* w2r = W1BT + (has2 ? (36+p2)*32 : 0);
      ull acc0 = lds64(&C0[2*p0]);
      ull acc1 = lds64(&C0[g1*72+2*p1]);
      ull acc2 = has2 ? lds64(&C0[72+2*p2]) : 0;
      float rres = 0.f;
      #pragma unroll 8
      for (int h=0;h<HDn;h++){
        float av = H2T[h*33+lane];
        ull vv = pk2(av,av);
        acc0 = fma2(vv, lds64(&w0r[h]), acc0);
        acc1 = fma2(vv, lds64(&w1r[h]), acc1);
        if (has2) acc2 = fma2(vv, lds64(&w2r[h]), acc2);
        if (isrp){ float2 wv = WHP[h]; rres = fmaf(av, (wp&1)? wv.y : wv.x, rres); }
      }
      float a,b;
      upk2(acc0,a,b); UB[(2*p0)*33+lane]=a; UB[(2*p0+1)*33+lane]=b;
      upk2(acc1,a,b); UB[(g1*72+2*p1)*33+lane]=a; UB[(g1*72+2*p1+1)*33+lane]=b;
      if (has2){ upk2(acc2,a,b); UB[(72+2*p2)*33+lane]=a; UB[(72+2*p2+1)*33+lane]=b; }
      if (isrp){
        int dim = wp-30;
        float r = rres + BHP[dim];
        float pn = POS[dim*32+lane] + r;
        POS[dim*32+lane]=pn; RELP[dim*32+lane]=r;
        out[((size_t)(t*Bn + base + lane))*2 + dim] = r;
        #pragma unroll
        for (int s=0;s<5;s++){
          unsigned m = s ? GMASK[s] : 0xFFFFFFFFu;
          float v = ((m>>lane)&1u) ? pn : 0.f;
          #pragma unroll
          for (int o=16;o;o>>=1) v += __shfl_xor_sync(0xFFFFFFFFu, v, o);
          if (lane==s) PSUM[s*2+dim]=v;
        }
      }
    }
    __syncthreads();

    // ---- gsum: masked sums of u_full via ubase + analytic q-sums ----
    if (tid < 720){
      int gi=tid/360; int r=tid-gi*360; int s=r/GHn, d=r-s*GHn;
      unsigned m = s ? GMASK[s] : 0xFFFFFFFFu;
      const float* ubcol = UB + (gi*72+d)*33;
      float acc=0.f;
      #pragma unroll
      for (int k=0;k<Pn;k++)
        acc += ((m>>k)&1u) ? ubcol[k] : 0.f;
      float2 wc = WCC[gi*GHn+d];
      acc = fmaf(PSUM[s*2], wc.x, fmaf(PSUM[s*2+1], wc.y, acc));
      GSUM[gi*360 + s*GHn + d]=acc;
    }
    __syncthreads();

    // ---- mix: U = ubase + q; MIXA row = [plane0: -q | plane1: .5u-q]; SU ----
    for (int id=tid; id<2304; id+=NT){
      int gi=id/1152; int r=id-gi*1152; int i=r/36, dp=r-i*36; int d0=2*dp;
      float ub0 = UB[(gi*72+d0)*33+i], ub1 = UB[(gi*72+d0+1)*33+i];
      float px = POS[i], py = POS[32+i];
      float4 wc = *(const float4*)&WCC[gi*GHn+d0];
      float q0 = px*wc.x + py*wc.y;
      float q1 = px*wc.z + py*wc.w;
      float u0 = ub0 + q0, u1 = ub1 + q1;
      *(ull*)&U[(gi*Pn+i)*USTR + d0] = pk2(u0,u1);
      float* P = MIXA + (gi*Pn+i)*144;
      *(ull*)&P[d0]    = pk2(-q0, -q1);
      *(ull*)&P[72+d0] = pk2(fmaf(0.5f,u0,-q0), fmaf(0.5f,u1,-q1));
      int g = GTMP[i];
      float ci = CINV[gi*Pn+i];
      float2 tt = *(const float2*)&GSUM[gi*360+d0];
      float2 gg = *(const float2*)&GSUM[gi*360+g*GHn+d0];
      float v0, v1;
      if (gi==0){ v0 = g? gg.x*ci : u0;               v1 = g? gg.y*ci : u1; }
      else      { v0 = g? (tt.x-gg.x+u0)*ci : tt.x*ci; v1 = g? (tt.y-gg.y+u1)*ci : tt.y*ci; }
      *(ull*)&SU[(gi*Pn+i)*GHn + d0] = pk2(v0,v1);
    }
    __syncthreads();

    // ---- Z: 32 warps, 2 pair-rows per thread (i1, i2=i1+16);
    //      shared u_j load + predicated SU patch + plane-pointer MIXA (bank-safe) ----
    {
      int j=lane, i1=(tid>>5)&15, gi=tid>>9, i2=i1+16;
      bool dg1=(j==i1), dg2=(j==i2);
      bool sf1 = (!dg1) && ((MSK[gi*Pn+i1]>>j)&1u);
      bool sf2 = (!dg2) && ((MSK[gi*Pn+i2]>>j)&1u);
      float cf1 = sf1?0.5f:1.0f, cf2 = sf2?0.5f:1.0f;
      const float4* pu  = (const float4*)(U  + (gi*Pn+j )*USTR);
      const float4* ps1 = (const float4*)(SU + (gi*Pn+i1)*GHn);
      const float4* ps2 = (const float4*)(SU + (gi*Pn+i2)*GHn);
      const float4* pm1 = (const float4*)(MIXA + (gi*Pn+i1)*144 + (sf1?72:0));
      const float4* pm2 = (const float4*)(MIXA + (gi*Pn+i2)*144 + (sf2?72:0));
      const ulonglong2* w2 = (const ulonglong2*)(W2p + gi*GHn*GOn);
      ull A0=0,A1=0,A2=0,A3=0, B0=0,B1=0,B2=0,B3=0;
      #pragma unroll 3
      for (int b4=0; b4<18; b4++){
        float4 a  = pu[b4];
        float4 a1 = dg1 ? ps1[b4] : a;
        float4 a2 = dg2 ? ps2[b4] : a;
        float4 m1 = pm1[b4];
        float4 m2 = pm2[b4];
        #pragma unroll
        for (int dd=0; dd<4; dd++){
          float h1v = fmaxf(fmaf(cf1, (&a1.x)[dd], (&m1.x)[dd]), 0.f);
          float h2v = fmaxf(fmaf(cf2, (&a2.x)[dd], (&m2.x)[dd]), 0.f);
          ull hh1=pk2(h1v,h1v), hh2=pk2(h2v,h2v);
          int d = b4*4+dd;
          ulonglong2 wA = w2[d*2], wB = w2[d*2+1];
          A0=fma2(hh1,wA.x,A0); A1=fma2(hh1,wA.y,A1);
          A2=fma2(hh1,wB.x,A2); A3=fma2(hh1,wB.y,A3);
          B0=fma2(hh2,wA.x,B0); B1=fma2(hh2,wA.y,B1);
          B2=fma2(hh2,wB.x,B2); B3=fma2(hh2,wB.y,B3);
        }
      }
      int jp1 = (j + 4*i1)&31;
      int jp2 = (j + 4*i2)&31;
      float* zr1=ZR + (gi*Pn+i1)*ZSTR + jp1*9;
      float* zr2=ZR + (gi*Pn+i2)*ZSTR + jp2*9;
      float x,y;
      upk2(A0,x,y); zr1[0]=x; zr1[1]=y;  upk2(A1,x,y); zr1[2]=x; zr1[3]=y;
      upk2(A2,x,y); zr1[4]=x; zr1[5]=y;  upk2(A3,x,y); zr1[6]=x; zr1[7]=y;
      upk2(B0,x,y); zr2[0]=x; zr2[1]=y;  upk2(B1,x,y); zr2[2]=x; zr2[3]=y;
      upk2(B2,x,y); zr2[4]=x; zr2[5]=y;  upk2(B3,x,y); zr2[6]=x; zr2[7]=y;
    }
    __syncthreads();

    // ---- layer-2 combine + relu + max over j (jp rotation matches writer) ----
    if (tid < 512){
      int gi=tid>>8, i=(tid>>3)&31, c=tid&7;
      const float* zrow = ZR + (gi*Pn+i)*ZSTR;
      unsigned mi = MSK[gi*Pn+i];
      float zii = zrow[((5*i)&31)*9+c];
      float sum = 0.f;
      float best = -3.4e38f;
      #pragma unroll
      for (int j=0;j<Pn;j++){
        int jp = (j + 4*i)&31;
        float z = zrow[jp*9+c];
        bool sbv = (mi>>j)&1u;
        sum += sbv ? z : 0.f;
        if (j!=i){
          float v = sbv ? (z+zii)*0.5f : z;
          best = fmaxf(best, v);
        }
      }
      best = fmaxf(best, sum*CINV[gi*Pn+i]);
      POOLT[(gi*GOn+c)*33 + i] = fmaxf(best, 0.0f);
    }
    __syncthreads();

    // ---- MLP layer 1: warp=mp, lane=p ----
    {
      int mp=wp, p=lane;
      ull acc = BM1[mp];
      const ulonglong2* wrow = WM1P + mp*24;
      #pragma unroll
      for (int k2=0;k2<16;k2++){
        ulonglong2 w = wrow[k2];
        float a0 = H2T[(2*k2)*33+p], a1 = H2T[(2*k2+1)*33+p];
        acc=fma2(pk2(a0,a0), w.x, acc);
        acc=fma2(pk2(a1,a1), w.y, acc);
      }
      #pragma unroll
      for (int k2=16;k2<24;k2++){
        ulonglong2 w = wrow[k2];
        float a0 = POOLT[(2*k2-32)*33+p], a1 = POOLT[(2*k2-31)*33+p];
        acc=fma2(pk2(a0,a0), w.x, acc);
        acc=fma2(pk2(a1,a1), w.y, acc);
      }
      float a,b; upk2(acc,a,b);
      MIDT[(2*mp)*33+p]=fmaxf(a,0.f);
      MIDT[(2*mp+1)*33+p]=fmaxf(b,0.f);
    }
    __syncthreads();

    // ---- MLP layer 2 (warps 0-15) || next-x embedding (warps 16-31) ----
    if (wp < 16){
      int hp=wp, p=lane;
      ull acc = BM2[hp];
      const ulonglong2* wrow = WM2P + hp*32;
      #pragma unroll 8
      for (int k2=0;k2<32;k2++){
        ulonglong2 w = wrow[k2];
        float a0 = MIDT[(2*k2)*33+p], a1 = MIDT[(2*k2+1)*33+p];
        acc=fma2(pk2(a0,a0), w.x, acc);
        acc=fma2(pk2(a1,a1), w.y, acc);
      }
      float a,b; upk2(acc,a,b);
      HIDT[(2*hp)*33+p]=fmaxf(a,0.f);
      HIDT[(2*hp+1)*33+p]=fmaxf(b,0.f);
    } else {
      int e = wp-16, p = lane;
      XVT[e*33+p] = fmaf(RELP[p], WSE[e],
                    fmaf(RELP[32+p], WSE[EDn+e], BSE[e]));
    }
    __syncthreads();
  }
}

extern "C" void kernel_launch(void* const* d_in, const int* in_sizes, int n_in,
                              void* d_out, int out_size)
{
  (void)in_sizes; (void)n_in; (void)out_size;
  const float* last_pos     = (const float*)d_in[0];
  const float* last_pos_rel = (const float*)d_in[1];
  const float* hh           = (const float*)d_in[2];
  const float* ch           = (const float*)d_in[3];
  /* d_in[4] = seq_start_end (int64) — uniform scenes, unused */
  const int*   end_group    = (const int*)d_in[5];
  const float* W_se  = (const float*)d_in[6];
  const float* b_se  = (const float*)d_in[7];
  const float* Wih   = (const float*)d_in[8];
  const float* Whh   = (const float*)d_in[9];
  const float* bih   = (const float*)d_in[10];
  const float* bhh   = (const float*)d_in[11];
  const float* W_hp  = (const float*)d_in[12];
  const float* b_hp  = (const float*)d_in[13];
  const float* W_pse = (const float*)d_in[14];
  const float* b_pse = (const float*)d_in[15];
  const float* W1a   = (const float*)d_in[16];
  const float* W2a   = (const float*)d_in[17];
  const float* W1b   = (const float*)d_in[18];
  const float* W2b   = (const float*)d_in[19];
  const float* W_m1  = (const float*)d_in[20];
  const float* b_m1  = (const float*)d_in[21];
  const float* W_m2  = (const float*)d_in[22];
  const float* b_m2  = (const float*)d_in[23];
  float* out = (float*)d_out;

  cudaFuncSetAttribute(dec_kernel, cudaFuncAttributeMaxDynamicSharedMemorySize, SMEM_TOTAL);
  dec_kernel<<<Sn, NT, SMEM_TOTAL>>>(
      last_pos, last_pos_rel, hh, ch, end_group,
      W_se, b_se, Wih, Whh, bih, bhh, W_hp, b_hp, W_pse, b_pse,
      W1a, W2a, W1b, W2b, W_m1, b_m1, W_m2, b_m2, out);
}

// round 15
// speedup vs baseline: 1.6818x; 1.6818x over previous
#include <cuda_runtime.h>
#include <math.h>

#define Sn 128
#define Pn 32
#define HDn 32
#define EDn 16
#define GHn 72
#define GOn 8
#define MDn 64
#define Tn 8
#define Bn (Sn*Pn)
#define NT 1024

typedef unsigned long long ull;

// ---- byte offsets into dynamic smem (16B aligned) ----
#define OFF_WL      0        // ulonglong2 [32][48]   24576
#define OFF_BIF     24576    // ull [32]              256
#define OFF_BGO     24832    // ull [32]              256
#define OFF_WHP     25088    // float2 [32]           256
#define OFF_BHP     25344    // float [2]             16
#define OFF_WSE     25360    // float [32]            128
#define OFF_BSE     25488    // float [16]            64
#define OFF_W1BT    25552    // float2 [2*36][32]     18432
#define OFF_WCC     43984    // float2 [2][72]        1152
#define OFF_C0      45136    // float [2][72]         576
#define OFF_WM1P    45712    // ulonglong2 [32][24]   12288
#define OFF_BM1     58000    // ull [32]              256
#define OFF_WM2P    58256    // ulonglong2 [16][32]   8192
#define OFF_BM2     66448    // ull [16]              128
#define OFF_W2      66576    // float [2][72][8]      4608   (per-d channel pairs)
#define OFF_H2T     71184    // float [32][33]        4224
#define OFF_HIDT    75408    // float [32][33]        4224
#define OFF_XVT     79632    // float [16][33]        2112
#define OFF_POS     81744    // float [2][32]         256
#define OFF_RELP    82000    // float [2][32]         256
#define OFF_PSUM    82256    // float [5][2]          64
#define OFF_GTMP    82320    // int [32]              128
#define OFF_MSK     82448    // unsigned [2][32]      256
#define OFF_CINV    82704    // float [2][32]         256
#define OFF_GMASK   82960    // unsigned [8]          48
#define OFF_U       83008    // float [64][76]        19456
#define OFF_MIXA    102464   // float [64][144]       36864  row: [plane0: -q | plane1: .5u-q]
#define OFF_SU      139328   // float [64][72]        18432
#define OFF_ZR      157760   // float [64][288]       73728
#define SMEM_TOTAL  231488
// overlays (lifetime-disjoint):
#define OFF_UB      OFF_ZR            // float [144][33] 19008  (ubase; dead before Z writes)
#define OFF_GSUM    (OFF_ZR+19456)    // float [2][5][72] 2880  (gsum->mix; dead before Z writes)
#define OFF_MIDT    OFF_SU            // float [64][33]  8448   (MLP1->MLP2; SU dead after Z)
#define OFF_POOLT   (OFF_SU+8448)     // float [16][33]  2112   (max->MLP1)

#define USTR 76
#define ZSTR 288

__device__ __forceinline__ ull pk2(float a, float b){
  ull r; asm("mov.b64 %0,{%1,%2};" : "=l"(r) : "f"(a), "f"(b)); return r;
}
__device__ __forceinline__ void upk2(ull v, float& a, float& b){
  asm("mov.b64 {%0,%1},%2;" : "=f"(a), "=f"(b) : "l"(v));
}
__device__ __forceinline__ ull fma2(ull a, ull b, ull c){
  ull r; asm("fma.rn.f32x2 %0,%1,%2,%3;" : "=l"(r) : "l"(a), "l"(b), "l"(c)); return r;
}
__device__ __forceinline__ ull lds64(const void* p){ return *reinterpret_cast<const ull*>(p); }

__device__ __forceinline__ float sigm(float x){ return 1.0f/(1.0f + __expf(-x)); }
__device__ __forceinline__ float tanh_f(float x){
  float t = __expf(-2.0f*fabsf(x));
  float r = (1.0f - t)/(1.0f + t);
  return copysignf(r, x);
}

__global__ __launch_bounds__(NT, 1)
void dec_kernel(const float* __restrict__ last_pos, const float* __restrict__ last_pos_rel,
                const float* __restrict__ hh, const float* __restrict__ ch,
                const int* __restrict__ end_group,
                const float* __restrict__ W_se, const float* __restrict__ b_se,
                const float* __restrict__ Wih, const float* __restrict__ Whh,
                const float* __restrict__ bih, const float* __restrict__ bhh,
                const float* __restrict__ W_hp, const float* __restrict__ b_hp,
                const float* __restrict__ W_pse, const float* __restrict__ b_pse,
                const float* __restrict__ W1a, const float* __restrict__ W2a,
                const float* __restrict__ W1b, const float* __restrict__ W2b,
                const float* __restrict__ W_m1, const float* __restrict__ b_m1,
                const float* __restrict__ W_m2, const float* __restrict__ b_m2,
                float* __restrict__ out)
{
  extern __shared__ char sb[];
  ulonglong2* WL   = (ulonglong2*)(sb+OFF_WL);
  ull*      BIF    = (ull*)     (sb+OFF_BIF);
  ull*      BGO    = (ull*)     (sb+OFF_BGO);
  float2*   WHP    = (float2*)  (sb+OFF_WHP);
  float*    BHP    = (float*)   (sb+OFF_BHP);
  float*    WSE    = (float*)   (sb+OFF_WSE);
  float*    BSE    = (float*)   (sb+OFF_BSE);
  float2*   W1BT   = (float2*)  (sb+OFF_W1BT);
  float2*   WCC    = (float2*)  (sb+OFF_WCC);
  float*    C0     = (float*)   (sb+OFF_C0);
  ulonglong2* WM1P = (ulonglong2*)(sb+OFF_WM1P);
  ull*      BM1    = (ull*)     (sb+OFF_BM1);
  ulonglong2* WM2P = (ulonglong2*)(sb+OFF_WM2P);
  ull*      BM2    = (ull*)     (sb+OFF_BM2);
  float*    W2p    = (float*)   (sb+OFF_W2);
  float*    H2T    = (float*)   (sb+OFF_H2T);
  float*    HIDT   = (float*)   (sb+OFF_HIDT);
  float*    XVT    = (float*)   (sb+OFF_XVT);
  float*    POS    = (float*)   (sb+OFF_POS);
  float*    RELP   = (float*)   (sb+OFF_RELP);
  float*    PSUM   = (float*)   (sb+OFF_PSUM);
  int*      GTMP   = (int*)     (sb+OFF_GTMP);
  unsigned* MSK    = (unsigned*)(sb+OFF_MSK);
  float*    CINV   = (float*)   (sb+OFF_CINV);
  unsigned* GMASK  = (unsigned*)(sb+OFF_GMASK);
  float*    U      = (float*)   (sb+OFF_U);
  float*    MIXA   = (float*)   (sb+OFF_MIXA);
  float*    SU     = (float*)   (sb+OFF_SU);
  float*    ZR     = (float*)   (sb+OFF_ZR);
  float*    UB     = (float*)   (sb+OFF_UB);
  float*    GSUM   = (float*)   (sb+OFF_GSUM);
  float*    MIDT   = (float*)   (sb+OFF_MIDT);
  float*    POOLT  = (float*)   (sb+OFF_POOLT);

  const int tid  = threadIdx.x;
  const int base = blockIdx.x * Pn;
  const int lane = tid & 31;
  const int wp   = tid >> 5;

  // ---------------- setup ----------------
  for (int i=tid;i<HDn*48;i+=NT){
    int h=i/48, k=i%48;
    float wi,wf,wg,wo;
    if (k<EDn){
      wi=Wih[h*EDn+k]; wf=Wih[(HDn+h)*EDn+k]; wg=Wih[(2*HDn+h)*EDn+k]; wo=Wih[(3*HDn+h)*EDn+k];
    } else {
      int kk=k-EDn;
      wi=Whh[h*HDn+kk]; wf=Whh[(HDn+h)*HDn+kk]; wg=Whh[(2*HDn+h)*HDn+kk]; wo=Whh[(3*HDn+h)*HDn+kk];
    }
    ulonglong2 w; w.x=pk2(wi,wf); w.y=pk2(wg,wo);
    WL[i]=w;
  }
  if (tid < HDn){
    int h=tid;
    BIF[h]=pk2(bih[h]+bhh[h], bih[HDn+h]+bhh[HDn+h]);
    BGO[h]=pk2(bih[2*HDn+h]+bhh[2*HDn+h], bih[3*HDn+h]+bhh[3*HDn+h]);
    WHP[h]=make_float2(W_hp[h*2], W_hp[h*2+1]);
  }
  if (tid<2*EDn) WSE[tid]=W_se[tid];
  if (tid<EDn)   BSE[tid]=b_se[tid];
  if (tid<2)     BHP[tid]=b_hp[tid];
  for (int i=tid;i<2*36*HDn;i+=NT){
    int gi=i/(36*HDn); int r=i%(36*HDn); int dp=r/HDn, h=r%HDn;
    const float* W1 = gi? W1b : W1a;
    W1BT[(gi*36+dp)*32+h]=make_float2(W1[(EDn+h)*GHn+2*dp], W1[(EDn+h)*GHn+2*dp+1]);
  }
  for (int i=tid;i<2*GHn;i+=NT){
    int gi=i/GHn; int d=i%GHn;
    const float* W1 = gi? W1b : W1a;
    float wc0=0.f, wc1=0.f, c00=0.f;
    #pragma unroll
    for (int k=0;k<EDn;k++){
      float w=W1[k*GHn+d];
      wc0 += W_pse[k]*w;
      wc1 += W_pse[EDn+k]*w;
      c00 += b_pse[k]*w;
    }
    WCC[i]=make_float2(wc0,wc1); C0[i]=c00;
  }
  // W2 plain per-d: W2p[gi][d][c]
  for (int i=tid;i<2*GHn*GOn;i+=NT){
    int gi=i/(GHn*GOn); int rc=i%(GHn*GOn);
    W2p[i] = (gi? W2b : W2a)[rc];
  }
  for (int i=tid;i<32*24;i+=NT){
    int mp=i/24, k2=i%24; int k0=2*k2;
    ulonglong2 w;
    w.x = pk2(W_m1[k0*MDn+2*mp],     W_m1[k0*MDn+2*mp+1]);
    w.y = pk2(W_m1[(k0+1)*MDn+2*mp], W_m1[(k0+1)*MDn+2*mp+1]);
    WM1P[i]=w;
  }
  if (tid<MDn/2) BM1[tid]=pk2(b_m1[2*tid], b_m1[2*tid+1]);
  for (int i=tid;i<16*32;i+=NT){
    int hp=i/32, k2=i%32; int k0=2*k2;
    ulonglong2 w;
    w.x = pk2(W_m2[k0*HDn+2*hp],     W_m2[k0*HDn+2*hp+1]);
    w.y = pk2(W_m2[(k0+1)*HDn+2*hp], W_m2[(k0+1)*HDn+2*hp+1]);
    WM2P[i]=w;
  }
  if (tid<16) BM2[tid]=pk2(b_m2[2*tid], b_m2[2*tid+1]);
  for (int i=tid;i<Pn*HDn;i+=NT){ int p=i>>5, h=i&31; HIDT[h*33+p]=hh[base*HDn+i]; }
  for (int i=tid;i<Pn*EDn;i+=NT){ int p=i>>4, e=i&15;
    float r0=last_pos_rel[(base+p)*2], r1=last_pos_rel[(base+p)*2+1];
    XVT[e*33+p] = r0*W_se[e] + r1*W_se[EDn+e] + b_se[e]; }
  if (tid<64){ int dim=tid>>5, p=tid&31; POS[dim*32+p]=last_pos[(base+p)*2+dim]; }
  if (tid<Pn) GTMP[tid]=end_group[base+tid];
  for (int i=tid;i<Pn*HDn;i+=NT) ZR[i]=ch[base*HDn+i];
  __syncthreads();

  float creg = ZR[lane*32 + wp];   // c-state in regs (p=lane, h=wp)
  if (tid < Pn){
    int gme = GTMP[tid];
    unsigned ms=0u, md=0u;
    #pragma unroll
    for (int j=0;j<Pn;j++){
      bool samev = ((gme==GTMP[j]) && (gme!=0)) || (j==tid);
      bool diffv = (!samev) || (j==tid);
      ms |= (samev?1u:0u) << j;
      md |= (diffv?1u:0u) << j;
    }
    MSK[tid]=ms; MSK[Pn+tid]=md;
    CINV[tid]=1.0f/(float)__popc(ms);
    CINV[Pn+tid]=1.0f/(float)__popc(md);
  }
  if (tid < 8){
    unsigned gm=0u;
    if (tid>=1 && tid<=4){
      for (int j=0;j<Pn;j++) if (GTMP[j]==tid) gm |= 1u<<j;
    }
    GMASK[tid]=gm;
  }
  __syncthreads();

  // ---------------- time loop ----------------
  for (int t=0; t<Tn; t++){
    // ---- LSTM: warp=h, lane=p ----
    {
      const int h=wp, p=lane;
      const ulonglong2* wrow = WL + h*48;
      ull aif = BIF[h];
      ull ago = BGO[h];
      #pragma unroll
      for (int k=0;k<EDn;k++){
        ulonglong2 wv = wrow[k];
        float av = XVT[k*33+p];
        ull vv = pk2(av,av);
        aif=fma2(vv,wv.x,aif); ago=fma2(vv,wv.y,ago);
      }
      #pragma unroll
      for (int k=0;k<HDn;k++){
        ulonglong2 wv = wrow[EDn+k];
        float av = HIDT[k*33+p];
        ull vv = pk2(av,av);
        aif=fma2(vv,wv.x,aif); ago=fma2(vv,wv.y,ago);
      }
      float ai,af,ag,ao; upk2(aif,ai,af); upk2(ago,ag,ao);
      float c2 = sigm(af)*creg + sigm(ai)*tanh_f(ag);
      float h2v = sigm(ao)*tanh_f(c2);
      creg = c2;
      H2T[h*33+p]=h2v;
    }
    __syncthreads();

    // ---- ubase fused: 2-3 (gi,dp) columns per warp, ONE H2 pass, .128 weight loads;
    //      warps 30/31 also accumulate rel_pos ----
    {
      const int p0 = wp;                         // it0: gi=0, dp=wp
      const int itB = wp+32; const int g1 = itB/36; const int p1 = itB-36*g1;
      const int p2 = wp+28;                      // it2: gi=1 (only wp<8)
      const bool has2 = (wp < 8);
      const bool isrp = (wp >= 30);
      const float2* w0r = W1BT + p0*32;
      const float2* w1r = W1BT + (g1*36+p1)*32;
      const float2* w2r = W1BT + (has2 ? (36+p2)*32 : 0);
      ull acc0 = lds64(&C0[2*p0]);
      ull acc1 = lds64(&C0[g1*72+2*p1]);
      ull acc2 = has2 ? lds64(&C0[72+2*p2]) : 0;
      float rres = 0.f;
      #pragma unroll 4
      for (int h2v=0; h2v<16; h2v++){
        float av0 = H2T[(2*h2v)*33+lane];
        float av1 = H2T[(2*h2v+1)*33+lane];
        ull v0 = pk2(av0,av0), v1 = pk2(av1,av1);
        ulonglong2 w0 = *(const ulonglong2*)&w0r[2*h2v];
        ulonglong2 w1 = *(const ulonglong2*)&w1r[2*h2v];
        acc0 = fma2(v0, w0.x, acc0); acc0 = fma2(v1, w0.y, acc0);
        acc1 = fma2(v0, w1.x, acc1); acc1 = fma2(v1, w1.y, acc1);
        if (has2){
          ulonglong2 w2v = *(const ulonglong2*)&w2r[2*h2v];
          acc2 = fma2(v0, w2v.x, acc2); acc2 = fma2(v1, w2v.y, acc2);
        }
        if (isrp){
          float2 wva = WHP[2*h2v], wvb = WHP[2*h2v+1];
          rres = fmaf(av0, (wp&1)? wva.y : wva.x, rres);
          rres = fmaf(av1, (wp&1)? wvb.y : wvb.x, rres);
        }
      }
      float a,b;
      upk2(acc0,a,b); UB[(2*p0)*33+lane]=a; UB[(2*p0+1)*33+lane]=b;
      upk2(acc1,a,b); UB[(g1*72+2*p1)*33+lane]=a; UB[(g1*72+2*p1+1)*33+lane]=b;
      if (has2){ upk2(acc2,a,b); UB[(72+2*p2)*33+lane]=a; UB[(72+2*p2+1)*33+lane]=b; }
      if (isrp){
        int dim = wp-30;
        float r = rres + BHP[dim];
        float pn = POS[dim*32+lane] + r;
        POS[dim*32+lane]=pn; RELP[dim*32+lane]=r;
        out[((size_t)(t*Bn + base + lane))*2 + dim] = r;
        #pragma unroll
        for (int s=0;s<5;s++){
          unsigned m = s ? GMASK[s] : 0xFFFFFFFFu;
          float v = ((m>>lane)&1u) ? pn : 0.f;
          #pragma unroll
          for (int o=16;o;o>>=1) v += __shfl_xor_sync(0xFFFFFFFFu, v, o);
          if (lane==s) PSUM[s*2+dim]=v;
        }
      }
    }
    __syncthreads();

    // ---- gsum: masked sums of u_full via ubase + analytic q-sums ----
    if (tid < 720){
      int gi=tid/360; int r=tid-gi*360; int s=r/GHn, d=r-s*GHn;
      unsigned m = s ? GMASK[s] : 0xFFFFFFFFu;
      const float* ubcol = UB + (gi*72+d)*33;
      float acc=0.f;
      #pragma unroll
      for (int k=0;k<Pn;k++)
        acc += ((m>>k)&1u) ? ubcol[k] : 0.f;
      float2 wc = WCC[gi*GHn+d];
      acc = fmaf(PSUM[s*2], wc.x, fmaf(PSUM[s*2+1], wc.y, acc));
      GSUM[gi*360 + s*GHn + d]=acc;
    }
    __syncthreads();

    // ---- mix: U = ubase + q; MIXA row = [plane0: -q | plane1: .5u-q]; SU ----
    for (int id=tid; id<2304; id+=NT){
      int gi=id/1152; int r=id-gi*1152; int i=r/36, dp=r-i*36; int d0=2*dp;
      float ub0 = UB[(gi*72+d0)*33+i], ub1 = UB[(gi*72+d0+1)*33+i];
      float px = POS[i], py = POS[32+i];
      float4 wc = *(const float4*)&WCC[gi*GHn+d0];
      float q0 = px*wc.x + py*wc.y;
      float q1 = px*wc.z + py*wc.w;
      float u0 = ub0 + q0, u1 = ub1 + q1;
      *(ull*)&U[(gi*Pn+i)*USTR + d0] = pk2(u0,u1);
      float* P = MIXA + (gi*Pn+i)*144;
      *(ull*)&P[d0]    = pk2(-q0, -q1);
      *(ull*)&P[72+d0] = pk2(fmaf(0.5f,u0,-q0), fmaf(0.5f,u1,-q1));
      int g = GTMP[i];
      float ci = CINV[gi*Pn+i];
      float2 tt = *(const float2*)&GSUM[gi*360+d0];
      float2 gg = *(const float2*)&GSUM[gi*360+g*GHn+d0];
      float v0, v1;
      if (gi==0){ v0 = g? gg.x*ci : u0;               v1 = g? gg.y*ci : u1; }
      else      { v0 = g? (tt.x-gg.x+u0)*ci : tt.x*ci; v1 = g? (tt.y-gg.y+u1)*ci : tt.y*ci; }
      *(ull*)&SU[(gi*Pn+i)*GHn + d0] = pk2(v0,v1);
    }
    __syncthreads();

    // ---- Z: 32 warps, 2 pair-rows per thread (i1, i2=i1+16);
    //      pure pointer operand selection (no per-element selects/predicated loads) ----
    {
      int j=lane, i1=(tid>>5)&15, gi=tid>>9, i2=i1+16;
      bool dg1=(j==i1), dg2=(j==i2);
      bool sf1 = (!dg1) && ((MSK[gi*Pn+i1]>>j)&1u);
      bool sf2 = (!dg2) && ((MSK[gi*Pn+i2]>>j)&1u);
      float cf1 = sf1?0.5f:1.0f, cf2 = sf2?0.5f:1.0f;
      const float4* pa1 = (const float4*)(dg1 ? (SU + (gi*Pn+i1)*GHn) : (U + (gi*Pn+j)*USTR));
      const float4* pa2 = (const float4*)(dg2 ? (SU + (gi*Pn+i2)*GHn) : (U + (gi*Pn+j)*USTR));
      const float4* pm1 = (const float4*)(MIXA + (gi*Pn+i1)*144 + (sf1?72:0));
      const float4* pm2 = (const float4*)(MIXA + (gi*Pn+i2)*144 + (sf2?72:0));
      const ulonglong2* w2 = (const ulonglong2*)(W2p + gi*GHn*GOn);
      ull A0=0,A1=0,A2=0,A3=0, B0=0,B1=0,B2=0,B3=0;
      #pragma unroll 3
      for (int b4=0; b4<18; b4++){
        float4 a1 = pa1[b4];
        float4 a2 = pa2[b4];
        float4 m1 = pm1[b4];
        float4 m2 = pm2[b4];
        #pragma unroll
        for (int dd=0; dd<4; dd++){
          float h1v = fmaxf(fmaf(cf1, (&a1.x)[dd], (&m1.x)[dd]), 0.f);
          float h2v = fmaxf(fmaf(cf2, (&a2.x)[dd], (&m2.x)[dd]), 0.f);
          ull hh1=pk2(h1v,h1v), hh2=pk2(h2v,h2v);
          int d = b4*4+dd;
          ulonglong2 wA = w2[d*2], wB = w2[d*2+1];
          A0=fma2(hh1,wA.x,A0); A1=fma2(hh1,wA.y,A1);
          A2=fma2(hh1,wB.x,A2); A3=fma2(hh1,wB.y,A3);
          B0=fma2(hh2,wA.x,B0); B1=fma2(hh2,wA.y,B1);
          B2=fma2(hh2,wB.x,B2); B3=fma2(hh2,wB.y,B3);
        }
      }
      int jp1 = (j + 4*i1)&31;
      int jp2 = (j + 4*i2)&31;
      float* zr1=ZR + (gi*Pn+i1)*ZSTR + jp1*9;
      float* zr2=ZR + (gi*Pn+i2)*ZSTR + jp2*9;
      float x,y;
      upk2(A0,x,y); zr1[0]=x; zr1[1]=y;  upk2(A1,x,y); zr1[2]=x; zr1[3]=y;
      upk2(A2,x,y); zr1[4]=x; zr1[5]=y;  upk2(A3,x,y); zr1[6]=x; zr1[7]=y;
      upk2(B0,x,y); zr2[0]=x; zr2[1]=y;  upk2(B1,x,y); zr2[2]=x; zr2[3]=y;
      upk2(B2,x,y); zr2[4]=x; zr2[5]=y;  upk2(B3,x,y); zr2[6]=x; zr2[7]=y;
    }
    __syncthreads();

    // ---- layer-2 combine + relu + max over j (jp rotation matches writer) ----
    if (tid < 512){
      int gi=tid>>8, i=(tid>>3)&31, c=tid&7;
      const float* zrow = ZR + (gi*Pn+i)*ZSTR;
      unsigned mi = MSK[gi*Pn+i];
      float zii = zrow[((5*i)&31)*9+c];
      float sum = 0.f;
      float best = -3.4e38f;
      #pragma unroll
      for (int j=0;j<Pn;j++){
        int jp = (j + 4*i)&31;
        float z = zrow[jp*9+c];
        bool sbv = (mi>>j)&1u;
        sum += sbv ? z : 0.f;
        if (j!=i){
          float v = sbv ? (z+zii)*0.5f : z;
          best = fmaxf(best, v);
        }
      }
      best = fmaxf(best, sum*CINV[gi*Pn+i]);
      POOLT[(gi*GOn+c)*33 + i] = fmaxf(best, 0.0f);
    }
    __syncthreads();

    // ---- MLP layer 1: warp=mp, lane=p ----
    {
      int mp=wp, p=lane;
      ull acc = BM1[mp];
      const ulonglong2* wrow = WM1P + mp*24;
      #pragma unroll
      for (int k2=0;k2<16;k2++){
        ulonglong2 w = wrow[k2];
        float a0 = H2T[(2*k2)*33+p], a1 = H2T[(2*k2+1)*33+p];
        acc=fma2(pk2(a0,a0), w.x, acc);
        acc=fma2(pk2(a1,a1), w.y, acc);
      }
      #pragma unroll
      for (int k2=16;k2<24;k2++){
        ulonglong2 w = wrow[k2];
        float a0 = POOLT[(2*k2-32)*33+p], a1 = POOLT[(2*k2-31)*33+p];
        acc=fma2(pk2(a0,a0), w.x, acc);
        acc=fma2(pk2(a1,a1), w.y, acc);
      }
      float a,b; upk2(acc,a,b);
      MIDT[(2*mp)*33+p]=fmaxf(a,0.f);
      MIDT[(2*mp+1)*33+p]=fmaxf(b,0.f);
    }
    __syncthreads();

    // ---- MLP layer 2 (warps 0-15) || next-x embedding (warps 16-31) ----
    if (wp < 16){
      int hp=wp, p=lane;
      ull acc = BM2[hp];
      const ulonglong2* wrow = WM2P + hp*32;
      #pragma unroll 8
      for (int k2=0;k2<32;k2++){
        ulonglong2 w = wrow[k2];
        float a0 = MIDT[(2*k2)*33+p], a1 = MIDT[(2*k2+1)*33+p];
        acc=fma2(pk2(a0,a0), w.x, acc);
        acc=fma2(pk2(a1,a1), w.y, acc);
      }
      float a,b; upk2(acc,a,b);
      HIDT[(2*hp)*33+p]=fmaxf(a,0.f);
      HIDT[(2*hp+1)*33+p]=fmaxf(b,0.f);
    } else {
      int e = wp-16, p = lane;
      XVT[e*33+p] = fmaf(RELP[p], WSE[e],
                    fmaf(RELP[32+p], WSE[EDn+e], BSE[e]));
    }
    __syncthreads();
  }
}

extern "C" void kernel_launch(void* const* d_in, const int* in_sizes, int n_in,
                              void* d_out, int out_size)
{
  (void)in_sizes; (void)n_in; (void)out_size;
  const float* last_pos     = (const float*)d_in[0];
  const float* last_pos_rel = (const float*)d_in[1];
  const float* hh           = (const float*)d_in[2];
  const float* ch           = (const float*)d_in[3];
  /* d_in[4] = seq_start_end (int64) — uniform scenes, unused */
  const int*   end_group    = (const int*)d_in[5];
  const float* W_se  = (const float*)d_in[6];
  const float* b_se  = (const float*)d_in[7];
  const float* Wih   = (const float*)d_in[8];
  const float* Whh   = (const float*)d_in[9];
  const float* bih   = (const float*)d_in[10];
  const float* bhh   = (const float*)d_in[11];
  const float* W_hp  = (const float*)d_in[12];
  const float* b_hp  = (const float*)d_in[13];
  const float* W_pse = (const float*)d_in[14];
  const float* b_pse = (const float*)d_in[15];
  const float* W1a   = (const float*)d_in[16];
  const float* W2a   = (const float*)d_in[17];
  const float* W1b   = (const float*)d_in[18];
  const float* W2b   = (const float*)d_in[19];
  const float* W_m1  = (const float*)d_in[20];
  const float* b_m1  = (const float*)d_in[21];
  const float* W_m2  = (const float*)d_in[22];
  const float* b_m2  = (const float*)d_in[23];
  float* out = (float*)d_out;

  cudaFuncSetAttribute(dec_kernel, cudaFuncAttributeMaxDynamicSharedMemorySize, SMEM_TOTAL);
  dec_kernel<<<Sn, NT, SMEM_TOTAL>>>(
      last_pos, last_pos_rel, hh, ch, end_group,
      W_se, b_se, Wih, Whh, bih, bhh, W_hp, b_hp, W_pse, b_pse,
      W1a, W2a, W1b, W2b, W_m1, b_m1, W_m2, b_m2, out);
}

// round 16
// speedup vs baseline: 1.7793x; 1.0580x over previous
#include <cuda_runtime.h>
#include <math.h>

#define Sn 128
#define Pn 32
#define HDn 32
#define EDn 16
#define GHn 72
#define GOn 8
#define MDn 64
#define Tn 8
#define Bn (Sn*Pn)
#define NT 1024

typedef unsigned long long ull;

// ---- byte offsets into dynamic smem (16B aligned) ----
#define OFF_WL      0        // ulonglong2 [32][48]   24576
#define OFF_BIF     24576    // ull [32]              256
#define OFF_BGO     24832    // ull [32]              256
#define OFF_WHP     25088    // float2 [32]           256
#define OFF_BHP     25344    // float [2]             16
#define OFF_WSE     25360    // float [32]            128
#define OFF_BSE     25488    // float [16]            64
#define OFF_W1BT    25552    // float2 [2*36][32]     18432
#define OFF_WCC     43984    // float2 [2][72]        1152
#define OFF_C0      45136    // float [2][72]         576
#define OFF_WM1P    45712    // ulonglong2 [32][24]   12288
#define OFF_BM1     58000    // ull [32]              256
#define OFF_WM2P    58256    // ulonglong2 [16][32]   8192
#define OFF_BM2     66448    // ull [16]              128
#define OFF_W2      66576    // float [2][72][8]      4608   (per-d channel pairs)
#define OFF_H2T     71184    // float [32][33]        4224
#define OFF_HIDT    75408    // float [32][33]        4224
#define OFF_XVT     79632    // float [16][33]        2112
#define OFF_POS     81744    // float [2][32]         256
#define OFF_RELP    82000    // float [2][32]         256
#define OFF_PSUM    82256    // float [5][2]          64
#define OFF_GTMP    82320    // int [32]              128
#define OFF_MSK     82448    // unsigned [2][32]      256
#define OFF_CINV    82704    // float [2][32]         256
#define OFF_GMASK   82960    // unsigned [8]          48
#define OFF_U       83008    // float [64][76]        19456
#define OFF_MIXA    102464   // float [64][216]       55296  row: [-q | .5u-q | su-q]
#define OFF_ZR      157760   // float [64][288]       73728
#define SMEM_TOTAL  231488
// overlays (lifetime-disjoint):
#define OFF_UB      OFF_ZR            // float [144][33] 19008  (ubase; dead before Z writes)
#define OFF_GSUM    (OFF_ZR+19456)    // float [2][5][72] 2880  (gsum->mix; dead before Z writes)
#define OFF_MIDT    OFF_MIXA          // float [64][33]  8448   (MLP1->MLP2; MIXA dead after Z)
#define OFF_POOLT   (OFF_MIXA+8448)   // float [16][33]  2112   (max->MLP1)

#define USTR 76
#define ZSTR 288
#define MSTR 216

__device__ __forceinline__ ull pk2(float a, float b){
  ull r; asm("mov.b64 %0,{%1,%2};" : "=l"(r) : "f"(a), "f"(b)); return r;
}
__device__ __forceinline__ void upk2(ull v, float& a, float& b){
  asm("mov.b64 {%0,%1},%2;" : "=f"(a), "=f"(b) : "l"(v));
}
__device__ __forceinline__ ull fma2(ull a, ull b, ull c){
  ull r; asm("fma.rn.f32x2 %0,%1,%2,%3;" : "=l"(r) : "l"(a), "l"(b), "l"(c)); return r;
}
__device__ __forceinline__ ull lds64(const void* p){ return *reinterpret_cast<const ull*>(p); }

__device__ __forceinline__ float sigm(float x){ return 1.0f/(1.0f + __expf(-x)); }
__device__ __forceinline__ float tanh_f(float x){
  float t = __expf(-2.0f*fabsf(x));
  float r = (1.0f - t)/(1.0f + t);
  return copysignf(r, x);
}

__global__ __launch_bounds__(NT, 1)
void dec_kernel(const float* __restrict__ last_pos, const float* __restrict__ last_pos_rel,
                const float* __restrict__ hh, const float* __restrict__ ch,
                const int* __restrict__ end_group,
                const float* __restrict__ W_se, const float* __restrict__ b_se,
                const float* __restrict__ Wih, const float* __restrict__ Whh,
                const float* __restrict__ bih, const float* __restrict__ bhh,
                const float* __restrict__ W_hp, const float* __restrict__ b_hp,
                const float* __restrict__ W_pse, const float* __restrict__ b_pse,
                const float* __restrict__ W1a, const float* __restrict__ W2a,
                const float* __restrict__ W1b, const float* __restrict__ W2b,
                const float* __restrict__ W_m1, const float* __restrict__ b_m1,
                const float* __restrict__ W_m2, const float* __restrict__ b_m2,
                float* __restrict__ out)
{
  extern __shared__ char sb[];
  ulonglong2* WL   = (ulonglong2*)(sb+OFF_WL);
  ull*      BIF    = (ull*)     (sb+OFF_BIF);
  ull*      BGO    = (ull*)     (sb+OFF_BGO);
  float2*   WHP    = (float2*)  (sb+OFF_WHP);
  float*    BHP    = (float*)   (sb+OFF_BHP);
  float*    WSE    = (float*)   (sb+OFF_WSE);
  float*    BSE    = (float*)   (sb+OFF_BSE);
  float2*   W1BT   = (float2*)  (sb+OFF_W1BT);
  float2*   WCC    = (float2*)  (sb+OFF_WCC);
  float*    C0     = (float*)   (sb+OFF_C0);
  ulonglong2* WM1P = (ulonglong2*)(sb+OFF_WM1P);
  ull*      BM1    = (ull*)     (sb+OFF_BM1);
  ulonglong2* WM2P = (ulonglong2*)(sb+OFF_WM2P);
  ull*      BM2    = (ull*)     (sb+OFF_BM2);
  float*    W2p    = (float*)   (sb+OFF_W2);
  float*    H2T    = (float*)   (sb+OFF_H2T);
  float*    HIDT   = (float*)   (sb+OFF_HIDT);
  float*    XVT    = (float*)   (sb+OFF_XVT);
  float*    POS    = (float*)   (sb+OFF_POS);
  float*    RELP   = (float*)   (sb+OFF_RELP);
  float*    PSUM   = (float*)   (sb+OFF_PSUM);
  int*      GTMP   = (int*)     (sb+OFF_GTMP);
  unsigned* MSK    = (unsigned*)(sb+OFF_MSK);
  float*    CINV   = (float*)   (sb+OFF_CINV);
  unsigned* GMASK  = (unsigned*)(sb+OFF_GMASK);
  float*    U      = (float*)   (sb+OFF_U);
  float*    MIXA   = (float*)   (sb+OFF_MIXA);
  float*    ZR     = (float*)   (sb+OFF_ZR);
  float*    UB     = (float*)   (sb+OFF_UB);
  float*    GSUM   = (float*)   (sb+OFF_GSUM);
  float*    MIDT   = (float*)   (sb+OFF_MIDT);
  float*    POOLT  = (float*)   (sb+OFF_POOLT);

  const int tid  = threadIdx.x;
  const int base = blockIdx.x * Pn;
  const int lane = tid & 31;
  const int wp   = tid >> 5;

  // ---------------- setup ----------------
  for (int i=tid;i<HDn*48;i+=NT){
    int h=i/48, k=i%48;
    float wi,wf,wg,wo;
    if (k<EDn){
      wi=Wih[h*EDn+k]; wf=Wih[(HDn+h)*EDn+k]; wg=Wih[(2*HDn+h)*EDn+k]; wo=Wih[(3*HDn+h)*EDn+k];
    } else {
      int kk=k-EDn;
      wi=Whh[h*HDn+kk]; wf=Whh[(HDn+h)*HDn+kk]; wg=Whh[(2*HDn+h)*HDn+kk]; wo=Whh[(3*HDn+h)*HDn+kk];
    }
    ulonglong2 w; w.x=pk2(wi,wf); w.y=pk2(wg,wo);
    WL[i]=w;
  }
  if (tid < HDn){
    int h=tid;
    BIF[h]=pk2(bih[h]+bhh[h], bih[HDn+h]+bhh[HDn+h]);
    BGO[h]=pk2(bih[2*HDn+h]+bhh[2*HDn+h], bih[3*HDn+h]+bhh[3*HDn+h]);
    WHP[h]=make_float2(W_hp[h*2], W_hp[h*2+1]);
  }
  if (tid<2*EDn) WSE[tid]=W_se[tid];
  if (tid<EDn)   BSE[tid]=b_se[tid];
  if (tid<2)     BHP[tid]=b_hp[tid];
  for (int i=tid;i<2*36*HDn;i+=NT){
    int gi=i/(36*HDn); int r=i%(36*HDn); int dp=r/HDn, h=r%HDn;
    const float* W1 = gi? W1b : W1a;
    W1BT[(gi*36+dp)*32+h]=make_float2(W1[(EDn+h)*GHn+2*dp], W1[(EDn+h)*GHn+2*dp+1]);
  }
  for (int i=tid;i<2*GHn;i+=NT){
    int gi=i/GHn; int d=i%GHn;
    const float* W1 = gi? W1b : W1a;
    float wc0=0.f, wc1=0.f, c00=0.f;
    #pragma unroll
    for (int k=0;k<EDn;k++){
      float w=W1[k*GHn+d];
      wc0 += W_pse[k]*w;
      wc1 += W_pse[EDn+k]*w;
      c00 += b_pse[k]*w;
    }
    WCC[i]=make_float2(wc0,wc1); C0[i]=c00;
  }
  // W2 plain per-d: W2p[gi][d][c]
  for (int i=tid;i<2*GHn*GOn;i+=NT){
    int gi=i/(GHn*GOn); int rc=i%(GHn*GOn);
    W2p[i] = (gi? W2b : W2a)[rc];
  }
  for (int i=tid;i<32*24;i+=NT){
    int mp=i/24, k2=i%24; int k0=2*k2;
    ulonglong2 w;
    w.x = pk2(W_m1[k0*MDn+2*mp],     W_m1[k0*MDn+2*mp+1]);
    w.y = pk2(W_m1[(k0+1)*MDn+2*mp], W_m1[(k0+1)*MDn+2*mp+1]);
    WM1P[i]=w;
  }
  if (tid<MDn/2) BM1[tid]=pk2(b_m1[2*tid], b_m1[2*tid+1]);
  for (int i=tid;i<16*32;i+=NT){
    int hp=i/32, k2=i%32; int k0=2*k2;
    ulonglong2 w;
    w.x = pk2(W_m2[k0*HDn+2*hp],     W_m2[k0*HDn+2*hp+1]);
    w.y = pk2(W_m2[(k0+1)*HDn+2*hp], W_m2[(k0+1)*HDn+2*hp+1]);
    WM2P[i]=w;
  }
  if (tid<16) BM2[tid]=pk2(b_m2[2*tid], b_m2[2*tid+1]);
  for (int i=tid;i<Pn*HDn;i+=NT){ int p=i>>5, h=i&31; HIDT[h*33+p]=hh[base*HDn+i]; }
  for (int i=tid;i<Pn*EDn;i+=NT){ int p=i>>4, e=i&15;
    float r0=last_pos_rel[(base+p)*2], r1=last_pos_rel[(base+p)*2+1];
    XVT[e*33+p] = r0*W_se[e] + r1*W_se[EDn+e] + b_se[e]; }
  if (tid<64){ int dim=tid>>5, p=tid&31; POS[dim*32+p]=last_pos[(base+p)*2+dim]; }
  if (tid<Pn) GTMP[tid]=end_group[base+tid];
  for (int i=tid;i<Pn*HDn;i+=NT) ZR[i]=ch[base*HDn+i];
  __syncthreads();

  float creg = ZR[lane*32 + wp];   // c-state in regs (p=lane, h=wp)
  if (tid < Pn){
    int gme = GTMP[tid];
    unsigned ms=0u, md=0u;
    #pragma unroll
    for (int j=0;j<Pn;j++){
      bool samev = ((gme==GTMP[j]) && (gme!=0)) || (j==tid);
      bool diffv = (!samev) || (j==tid);
      ms |= (samev?1u:0u) << j;
      md |= (diffv?1u:0u) << j;
    }
    MSK[tid]=ms; MSK[Pn+tid]=md;
    CINV[tid]=1.0f/(float)__popc(ms);
    CINV[Pn+tid]=1.0f/(float)__popc(md);
  }
  if (tid < 8){
    unsigned gm=0u;
    if (tid>=1 && tid<=4){
      for (int j=0;j<Pn;j++) if (GTMP[j]==tid) gm |= 1u<<j;
    }
    GMASK[tid]=gm;
  }
  __syncthreads();

  // ---------------- time loop ----------------
  for (int t=0; t<Tn; t++){
    // ---- LSTM: warp=h, lane=p ----
    {
      const int h=wp, p=lane;
      const ulonglong2* wrow = WL + h*48;
      ull aif = BIF[h];
      ull ago = BGO[h];
      #pragma unroll
      for (int k=0;k<EDn;k++){
        ulonglong2 wv = wrow[k];
        float av = XVT[k*33+p];
        ull vv = pk2(av,av);
        aif=fma2(vv,wv.x,aif); ago=fma2(vv,wv.y,ago);
      }
      #pragma unroll
      for (int k=0;k<HDn;k++){
        ulonglong2 wv = wrow[EDn+k];
        float av = HIDT[k*33+p];
        ull vv = pk2(av,av);
        aif=fma2(vv,wv.x,aif); ago=fma2(vv,wv.y,ago);
      }
      float ai,af,ag,ao; upk2(aif,ai,af); upk2(ago,ag,ao);
      float c2 = sigm(af)*creg + sigm(ai)*tanh_f(ag);
      float h2v = sigm(ao)*tanh_f(c2);
      creg = c2;
      H2T[h*33+p]=h2v;
    }
    __syncthreads();

    // ---- ubase fused: 2-3 (gi,dp) columns per warp, ONE H2 pass, .128 weight loads;
    //      warps 30/31 also accumulate rel_pos ----
    {
      const int p0 = wp;                         // it0: gi=0, dp=wp
      const int itB = wp+32; const int g1 = itB/36; const int p1 = itB-36*g1;
      const int p2 = wp+28;                      // it2: gi=1 (only wp<8)
      const bool has2 = (wp < 8);
      const bool isrp = (wp >= 30);
      const float2* w0r = W1BT + p0*32;
      const float2* w1r = W1BT + (g1*36+p1)*32;
      const float2* w2r = W1BT + (has2 ? (36+p2)*32 : 0);
      ull acc0 = lds64(&C0[2*p0]);
      ull acc1 = lds64(&C0[g1*72+2*p1]);
      ull acc2 = has2 ? lds64(&C0[72+2*p2]) : 0;
      float rres = 0.f;
      #pragma unroll 4
      for (int h2v=0; h2v<16; h2v++){
        float av0 = H2T[(2*h2v)*33+lane];
        float av1 = H2T[(2*h2v+1)*33+lane];
        ull v0 = pk2(av0,av0), v1 = pk2(av1,av1);
        ulonglong2 w0 = *(const ulonglong2*)&w0r[2*h2v];
        ulonglong2 w1 = *(const ulonglong2*)&w1r[2*h2v];
        acc0 = fma2(v0, w0.x, acc0); acc0 = fma2(v1, w0.y, acc0);
        acc1 = fma2(v0, w1.x, acc1); acc1 = fma2(v1, w1.y, acc1);
        if (has2){
          ulonglong2 w2v = *(const ulonglong2*)&w2r[2*h2v];
          acc2 = fma2(v0, w2v.x, acc2); acc2 = fma2(v1, w2v.y, acc2);
        }
        if (isrp){
          float2 wva = WHP[2*h2v], wvb = WHP[2*h2v+1];
          rres = fmaf(av0, (wp&1)? wva.y : wva.x, rres);
          rres = fmaf(av1, (wp&1)? wvb.y : wvb.x, rres);
        }
      }
      float a,b;
      upk2(acc0,a,b); UB[(2*p0)*33+lane]=a; UB[(2*p0+1)*33+lane]=b;
      upk2(acc1,a,b); UB[(g1*72+2*p1)*33+lane]=a; UB[(g1*72+2*p1+1)*33+lane]=b;
      if (has2){ upk2(acc2,a,b); UB[(72+2*p2)*33+lane]=a; UB[(72+2*p2+1)*33+lane]=b; }
      if (isrp){
        int dim = wp-30;
        float r = rres + BHP[dim];
        float pn = POS[dim*32+lane] + r;
        POS[dim*32+lane]=pn; RELP[dim*32+lane]=r;
        out[((size_t)(t*Bn + base + lane))*2 + dim] = r;
        #pragma unroll
        for (int s=0;s<5;s++){
          unsigned m = s ? GMASK[s] : 0xFFFFFFFFu;
          float v = ((m>>lane)&1u) ? pn : 0.f;
          #pragma unroll
          for (int o=16;o;o>>=1) v += __shfl_xor_sync(0xFFFFFFFFu, v, o);
          if (lane==s) PSUM[s*2+dim]=v;
        }
      }
    }
    __syncthreads();

    // ---- gsum: masked sums of u_full via ubase + analytic q-sums ----
    if (tid < 720){
      int gi=tid/360; int r=tid-gi*360; int s=r/GHn, d=r-s*GHn;
      unsigned m = s ? GMASK[s] : 0xFFFFFFFFu;
      const float* ubcol = UB + (gi*72+d)*33;
      float acc=0.f;
      #pragma unroll
      for (int k=0;k<Pn;k++)
        acc += ((m>>k)&1u) ? ubcol[k] : 0.f;
      float2 wc = WCC[gi*GHn+d];
      acc = fmaf(PSUM[s*2], wc.x, fmaf(PSUM[s*2+1], wc.y, acc));
      GSUM[gi*360 + s*GHn + d]=acc;
    }
    __syncthreads();

    // ---- mix: U = ubase + q; MIXA row = [-q | .5u-q | su-q] ----
    for (int id=tid; id<2304; id+=NT){
      int gi=id/1152; int r=id-gi*1152; int i=r/36, dp=r-i*36; int d0=2*dp;
      float ub0 = UB[(gi*72+d0)*33+i], ub1 = UB[(gi*72+d0+1)*33+i];
      float px = POS[i], py = POS[32+i];
      float4 wc = *(const float4*)&WCC[gi*GHn+d0];
      float q0 = px*wc.x + py*wc.y;
      float q1 = px*wc.z + py*wc.w;
      float u0 = ub0 + q0, u1 = ub1 + q1;
      *(ull*)&U[(gi*Pn+i)*USTR + d0] = pk2(u0,u1);
      float* P = MIXA + (gi*Pn+i)*MSTR;
      *(ull*)&P[d0]    = pk2(-q0, -q1);
      *(ull*)&P[72+d0] = pk2(fmaf(0.5f,u0,-q0), fmaf(0.5f,u1,-q1));
      int g = GTMP[i];
      float ci = CINV[gi*Pn+i];
      float2 tt = *(const float2*)&GSUM[gi*360+d0];
      float2 gg = *(const float2*)&GSUM[gi*360+g*GHn+d0];
      float v0, v1;
      if (gi==0){ v0 = g? gg.x*ci : u0;               v1 = g? gg.y*ci : u1; }
      else      { v0 = g? (tt.x-gg.x+u0)*ci : tt.x*ci; v1 = g? (tt.y-gg.y+u1)*ci : tt.y*ci; }
      *(ull*)&P[144+d0] = pk2(v0-q0, v1-q1);
    }
    __syncthreads();

    // ---- Z: 32 warps, 2 pair-rows per thread (i1, i2=i1+16);
    //      single shared u_j operand; diag via plane2 with cf=0 ----
    {
      int j=lane, i1=(tid>>5)&15, gi=tid>>9, i2=i1+16;
      bool dg1=(j==i1), dg2=(j==i2);
      bool sf1 = (!dg1) && ((MSK[gi*Pn+i1]>>j)&1u);
      bool sf2 = (!dg2) && ((MSK[gi*Pn+i2]>>j)&1u);
      float cf1 = dg1?0.f:(sf1?0.5f:1.0f);
      float cf2 = dg2?0.f:(sf2?0.5f:1.0f);
      const float4* pa  = (const float4*)(U + (gi*Pn+j)*USTR);
      const float4* pm1 = (const float4*)(MIXA + (gi*Pn+i1)*MSTR + (dg1?144:(sf1?72:0)));
      const float4* pm2 = (const float4*)(MIXA + (gi*Pn+i2)*MSTR + (dg2?144:(sf2?72:0)));
      const ulonglong2* w2 = (const ulonglong2*)(W2p + gi*GHn*GOn);
      ull A0=0,A1=0,A2=0,A3=0, B0=0,B1=0,B2=0,B3=0;
      #pragma unroll 3
      for (int b4=0; b4<18; b4++){
        float4 a  = pa[b4];
        float4 m1 = pm1[b4];
        float4 m2 = pm2[b4];
        #pragma unroll
        for (int dd=0; dd<4; dd++){
          float h1v = fmaxf(fmaf(cf1, (&a.x)[dd], (&m1.x)[dd]), 0.f);
          float h2v = fmaxf(fmaf(cf2, (&a.x)[dd], (&m2.x)[dd]), 0.f);
          ull hh1=pk2(h1v,h1v), hh2=pk2(h2v,h2v);
          int d = b4*4+dd;
          ulonglong2 wA = w2[d*2], wB = w2[d*2+1];
          A0=fma2(hh1,wA.x,A0); A1=fma2(hh1,wA.y,A1);
          A2=fma2(hh1,wB.x,A2); A3=fma2(hh1,wB.y,A3);
          B0=fma2(hh2,wA.x,B0); B1=fma2(hh2,wA.y,B1);
          B2=fma2(hh2,wB.x,B2); B3=fma2(hh2,wB.y,B3);
        }
      }
      int jp1 = (j + 4*i1)&31;
      int jp2 = (j + 4*i2)&31;
      float* zr1=ZR + (gi*Pn+i1)*ZSTR + jp1*9;
      float* zr2=ZR + (gi*Pn+i2)*ZSTR + jp2*9;
      float x,y;
      upk2(A0,x,y); zr1[0]=x; zr1[1]=y;  upk2(A1,x,y); zr1[2]=x; zr1[3]=y;
      upk2(A2,x,y); zr1[4]=x; zr1[5]=y;  upk2(A3,x,y); zr1[6]=x; zr1[7]=y;
      upk2(B0,x,y); zr2[0]=x; zr2[1]=y;  upk2(B1,x,y); zr2[2]=x; zr2[3]=y;
      upk2(B2,x,y); zr2[4]=x; zr2[5]=y;  upk2(B3,x,y); zr2[6]=x; zr2[7]=y;
    }
    __syncthreads();

    // ---- layer-2 combine + relu + max over j (jp rotation matches writer) ----
    if (tid < 512){
      int gi=tid>>8, i=(tid>>3)&31, c=tid&7;
      const float* zrow = ZR + (gi*Pn+i)*ZSTR;
      unsigned mi = MSK[gi*Pn+i];
      float zii = zrow[((5*i)&31)*9+c];
      float sum = 0.f;
      float best = -3.4e38f;
      #pragma unroll
      for (int j=0;j<Pn;j++){
        int jp = (j + 4*i)&31;
        float z = zrow[jp*9+c];
        bool sbv = (mi>>j)&1u;
        sum += sbv ? z : 0.f;
        if (j!=i){
          float v = sbv ? (z+zii)*0.5f : z;
          best = fmaxf(best, v);
        }
      }
      best = fmaxf(best, sum*CINV[gi*Pn+i]);
      POOLT[(gi*GOn+c)*33 + i] = fmaxf(best, 0.0f);
    }
    __syncthreads();

    // ---- MLP layer 1: warp=mp, lane=p ----
    {
      int mp=wp, p=lane;
      ull acc = BM1[mp];
      const ulonglong2* wrow = WM1P + mp*24;
      #pragma unroll
      for (int k2=0;k2<16;k2++){
        ulonglong2 w = wrow[k2];
        float a0 = H2T[(2*k2)*33+p], a1 = H2T[(2*k2+1)*33+p];
        acc=fma2(pk2(a0,a0), w.x, acc);
        acc=fma2(pk2(a1,a1), w.y, acc);
      }
      #pragma unroll
      for (int k2=16;k2<24;k2++){
        ulonglong2 w = wrow[k2];
        float a0 = POOLT[(2*k2-32)*33+p], a1 = POOLT[(2*k2-31)*33+p];
        acc=fma2(pk2(a0,a0), w.x, acc);
        acc=fma2(pk2(a1,a1), w.y, acc);
      }
      float a,b; upk2(acc,a,b);
      MIDT[(2*mp)*33+p]=fmaxf(a,0.f);
      MIDT[(2*mp+1)*33+p]=fmaxf(b,0.f);
    }
    __syncthreads();

    // ---- MLP layer 2 (warps 0-15) || next-x embedding (warps 16-31) ----
    if (wp < 16){
      int hp=wp, p=lane;
      ull acc = BM2[hp];
      const ulonglong2* wrow = WM2P + hp*32;
      #pragma unroll 8
      for (int k2=0;k2<32;k2++){
        ulonglong2 w = wrow[k2];
        float a0 = MIDT[(2*k2)*33+p], a1 = MIDT[(2*k2+1)*33+p];
        acc=fma2(pk2(a0,a0), w.x, acc);
        acc=fma2(pk2(a1,a1), w.y, acc);
      }
      float a,b; upk2(acc,a,b);
      HIDT[(2*hp)*33+p]=fmaxf(a,0.f);
      HIDT[(2*hp+1)*33+p]=fmaxf(b,0.f);
    } else {
      int e = wp-16, p = lane;
      XVT[e*33+p] = fmaf(RELP[p], WSE[e],
                    fmaf(RELP[32+p], WSE[EDn+e], BSE[e]));
    }
    __syncthreads();
  }
}

extern "C" void kernel_launch(void* const* d_in, const int* in_sizes, int n_in,
                              void* d_out, int out_size)
{
  (void)in_sizes; (void)n_in; (void)out_size;
  const float* last_pos     = (const float*)d_in[0];
  const float* last_pos_rel = (const float*)d_in[1];
  const float* hh           = (const float*)d_in[2];
  const float* ch           = (const float*)d_in[3];
  /* d_in[4] = seq_start_end (int64) — uniform scenes, unused */
  const int*   end_group    = (const int*)d_in[5];
  const float* W_se  = (const float*)d_in[6];
  const float* b_se  = (const float*)d_in[7];
  const float* Wih   = (const float*)d_in[8];
  const float* Whh   = (const float*)d_in[9];
  const float* bih   = (const float*)d_in[10];
  const float* bhh   = (const float*)d_in[11];
  const float* W_hp  = (const float*)d_in[12];
  const float* b_hp  = (const float*)d_in[13];
  const float* W_pse = (const float*)d_in[14];
  const float* b_pse = (const float*)d_in[15];
  const float* W1a   = (const float*)d_in[16];
  const float* W2a   = (const float*)d_in[17];
  const float* W1b   = (const float*)d_in[18];
  const float* W2b   = (const float*)d_in[19];
  const float* W_m1  = (const float*)d_in[20];
  const float* b_m1  = (const float*)d_in[21];
  const float* W_m2  = (const float*)d_in[22];
  const float* b_m2  = (const float*)d_in[23];
  float* out = (float*)d_out;

  cudaFuncSetAttribute(dec_kernel, cudaFuncAttributeMaxDynamicSharedMemorySize, SMEM_TOTAL);
  dec_kernel<<<Sn, NT, SMEM_TOTAL>>>(
      last_pos, last_pos_rel, hh, ch, end_group,
      W_se, b_se, Wih, Whh, bih, bhh, W_hp, b_hp, W_pse, b_pse,
      W1a, W2a, W1b, W2b, W_m1, b_m1, W_m2, b_m2, out);
}